// round 13
// baseline (speedup 1.0000x reference)
#include <cuda_runtime.h>

#define BT 640
#define NWARP 20
#define RHO_F 1060.0f
#define CCFL_F 0.9f
#define EPS_AF 1e-6f
#define MAX_CTA 160
#define MAX_T 256

// Persistent scratch.
// g_sync[t] = {smax_bits (red.max), arrive_count (red.add)} — one 8B word per step.
__device__ uint2  g_sync[MAX_T];
__device__ float4 g_edgeL[2][MAX_CTA];   // [buf][cta] first-point {A,Q,FQ,tag}
__device__ float4 g_edgeR[2][MAX_CTA];   // [buf][cta] last-point  {A,Q,FQ,tag}

__device__ __forceinline__ uint2 ld_acq_v2(const uint2* p) {
    uint2 v;
    asm volatile("ld.acquire.gpu.global.v2.u32 {%0,%1}, [%2];"
                 : "=r"(v.x), "=r"(v.y) : "l"(p) : "memory");
    return v;
}
__device__ __forceinline__ float4 ld_acq_v4(const float4* p) {
    float4 v;
    asm volatile("ld.acquire.gpu.global.v4.f32 {%0,%1,%2,%3}, [%4];"
                 : "=f"(v.x), "=f"(v.y), "=f"(v.z), "=f"(v.w) : "l"(p) : "memory");
    return v;
}
__device__ __forceinline__ void st_weak_v4(float4* p, float4 v) {
    asm volatile("st.global.v4.f32 [%0], {%1,%2,%3,%4};"
                 :: "l"(p), "f"(v.x), "f"(v.y), "f"(v.z), "f"(v.w) : "memory");
}
__device__ __forceinline__ void red_max_relaxed(unsigned* p, unsigned v) {
    asm volatile("red.relaxed.gpu.global.max.u32 [%0], %1;" :: "l"(p), "r"(v) : "memory");
}
__device__ __forceinline__ void red_add_release(unsigned* p, unsigned v) {
    asm volatile("red.release.gpu.global.add.u32 [%0], %1;" :: "l"(p), "r"(v) : "memory");
}
__device__ __forceinline__ float sqrt_fast(float x) {
    float y; asm("sqrt.approx.f32 %0, %1;" : "=f"(y) : "f"(x)); return y;
}

__global__ void sim_init_kernel() {
    int i = blockIdx.x * blockDim.x + threadIdx.x;
    if (i < MAX_T) g_sync[i] = make_uint2(0u, 0u);
    if (i < 2 * MAX_CTA) {   // reset edge tags (replay safety)
        float tg = __int_as_float(-1);
        ((float4*)g_edgeL)[i].w = tg;
        ((float4*)g_edgeR)[i].w = tg;
    }
}

__global__ void __launch_bounds__(BT, 1) sim_kernel(
    const float* __restrict__ Rs,
    const float* __restrict__ sim_dat,      // (2, M)
    const float* __restrict__ sdc,          // (11, M)
    const float* __restrict__ input_data,   // (T,)
    const int*   __restrict__ strides,      // (3, 2)
    float*       __restrict__ out,          // (T, 3)
    int M, int T)
{
    __shared__ float4 sAQF[2][BT];    // packed state {A, Q, FQ, _}
    __shared__ int    wmax[NWARP];
    __shared__ float  bc[9];          // [0]=lam  [3..5]=left AQF  [6..8]=right AQF
    __shared__ float  sIn[256];

    const int tid  = threadIdx.x;
    const int lane = tid & 31;
    const int wid  = tid >> 5;
    const int cta  = blockIdx.x;
    const int nCTA = gridDim.x;
    const int gi   = cta * BT + tid;
    const bool active = gi < M;

    for (int i = tid; i < T; i += BT) sIn[i] = input_data[i];
    if (tid >= 3 && tid < 9) bc[tid] = 1.0f;   // defaults; domain-boundary CTAs never overwrite

    const int st0 = strides[0], st1 = strides[2], st2 = strides[4];
    const int en0 = strides[1] - 1, en1 = strides[3] - 1, en2 = strides[5] - 1;
    const int mid0 = (strides[0] + strides[1]) >> 1;
    const int mid1 = (strides[2] + strides[3]) >> 1;
    const int mid2 = (strides[4] + strides[5]) >> 1;

    const bool is_start = active && (gi == st0 || gi == st1 || gi == st2);
    const bool is_end   = active && (gi == en0 || gi == en1 || gi == en2);
    const bool interior = active && gi > 0 && gi < M - 1;
    const int  midv = (gi == mid0) ? 0 : (gi == mid1) ? 1 : (gi == mid2) ? 2 : -1;

    float A = 1.0f, Q = 0.0f, invA0 = 1.0f, beta = 1.0f, Rtot = 1.0f;
    if (active) {
        A = fmaxf(sim_dat[gi], EPS_AF);
        Q = 0.1f * sim_dat[M + gi];
        invA0 = __fdividef(1.0f, sdc[gi] + 0.5f);
        beta = sdc[M + gi] + 1.0f;
        if (is_end) {
            float R1 = sdc[7 * M + gi] + 0.5f;
            float R2 = sdc[8 * M + gi] + 0.5f;
            bool m1 = (gi >= strides[2]) && (gi < strides[3]);
            bool m2 = (gi >= strides[4]) && (gi < strides[5]);
            float rsv[4];
#pragma unroll
            for (int j = 0; j < 4; j++) {
                float x = Rs[j];
                rsv[j] = fmaxf(x, 0.0f) + log1pf(expf(-fabsf(x)));   // softplus
            }
            if (m1)      { R1 *= rsv[0]; R2 *= rsv[1]; }
            else if (m2) { R1 *= rsv[2]; R2 *= rsv[3]; }
            Rtot = R1 + R2;
        }
    }
    const float cc  = beta * (0.5f / RHO_F);
    const float fqc = beta * invA0 * (1.0f / (3.0f * RHO_F));

    // ---- prologue: state-0 derived quantities ----
    float sq = 1.0f, FQ = 0.0f, sval = 0.0f;
    if (active) {
        sq = sqrt_fast(A * invA0);
        float u = __fdividef(Q, A);
        float c = sqrt_fast(cc * sq);
        sval = fabsf(u) + c;
        FQ = Q * u + fqc * A * sq;
    }
    sAQF[0][tid] = make_float4(A, Q, FQ, 0.f);
    {
        int wv = __reduce_max_sync(0xFFFFFFFFu, __float_as_int(sval));
        if (lane == 0) wmax[wid] = wv;
    }
    __syncthreads();
    if (wid == 0) {
        int v = __reduce_max_sync(0xFFFFFFFFu, (lane < NWARP) ? wmax[lane] : 0);
        if (lane == 0) {
            red_max_relaxed(&g_sync[0].x, (unsigned)v);
            red_add_release(&g_sync[0].y, 1u);
        }
    }
    // edge publish AFTER the arrive — consumers gate on the in-word tag, so the
    // count never needed to order these; keeps the release RED un-held.
    if (tid == 0)      st_weak_v4(&g_edgeL[0][cta], make_float4(A, Q, FQ, __int_as_float(0)));
    if (tid == BT - 1) st_weak_v4(&g_edgeR[0][cta], make_float4(A, Q, FQ, __int_as_float(0)));

    const bool haveL = tid > 0, haveR = tid < BT - 1;
    const bool pollL = (cta > 0), pollR = (cta + 1 < nCTA);

    for (int t = 0; t < T; ++t) {
        const int b = t & 1, nb = b ^ 1;

        // ---- PRE-BARRIER: stencil terms not needing lam ----
        // lam*0.5*smax = 0.45 (constant):
        //   A_new = [A + 0.45*(Ar-2A+Al)] - lam*0.5*(Qr-Ql)
        //   Q_new = [Q + 0.45*(Qr-2Q+Ql)] - lam*0.5*(Fr-Fl)
        float4 Lh, Rh;
        float dA1 = 0.f, dQ1 = 0.f, cA = A, cQ = Q;
        if (haveL && haveR) {
            Lh = sAQF[b][tid - 1]; Rh = sAQF[b][tid + 1];
            dA1 = 0.5f * (Rh.y - Lh.y);
            dQ1 = 0.5f * (Rh.z - Lh.z);
            cA  = fmaf(0.45f, Rh.x - 2.0f * A + Lh.x, A);
            cQ  = fmaf(0.45f, Rh.y - 2.0f * Q + Lh.y, Q);
        }
        const float P = beta * (sq - 1.0f);
        if (midv >= 0) out[t * 3 + midv] = P;
        const float Qend = is_end ? __fdividef(P, Rtot) : 0.0f;

        // ---- barrier + prefetch: three independent scalar spins in separate warps ----
        // Simple dependent spins: self-throttled to one L2 round trip per probe.
        if (tid == 0) {
            uint2 s;
            do { s = ld_acq_v2(&g_sync[t]); } while (s.y != (unsigned)nCTA);
            bc[0] = __fdividef(CCFL_F, __uint_as_float(s.x));   // ship lam, not smax
        } else if (tid == 32 && pollL) {
            float4 e;
            do { e = ld_acq_v4(&g_edgeR[b][cta - 1]); } while (__float_as_int(e.w) != t);
            bc[3] = e.x; bc[4] = e.y; bc[5] = e.z;
        } else if (tid == 64 && pollR) {
            float4 e;
            do { e = ld_acq_v4(&g_edgeL[b][cta + 1]); } while (__float_as_int(e.w) != t);
            bc[6] = e.x; bc[7] = e.y; bc[8] = e.z;
        }
        __syncthreads();
        const float lam = bc[0];

        // edge threads: halo staged in bc — zero L2 on the post-barrier path
        if (!haveL || !haveR) {
            if (!haveL) { Lh.x = bc[3]; Lh.y = bc[4]; Lh.z = bc[5]; }
            else        { Lh = sAQF[b][tid - 1]; }
            if (!haveR) { Rh.x = bc[6]; Rh.y = bc[7]; Rh.z = bc[8]; }
            else        { Rh = sAQF[b][tid + 1]; }
            dA1 = 0.5f * (Rh.y - Lh.y);
            dQ1 = 0.5f * (Rh.z - Lh.z);
            cA  = fmaf(0.45f, Rh.x - 2.0f * A + Lh.x, A);
            cQ  = fmaf(0.45f, Rh.y - 2.0f * Q + Lh.y, Q);
        }

        // ---- POST-BARRIER: short chain ----
        float An = interior ? cA - lam * dA1 : A;
        float Qn = interior ? cQ - lam * dQ1 : Q;
        if (is_start) Qn = sIn[t];
        if (is_end)   Qn = Qend;
        An = fmaxf(An, EPS_AF);

        float snew = 0.0f;
        if (active) {
            A = An; Q = Qn;
            sq = sqrt_fast(A * invA0);
            float u = __fdividef(Q, A);
            float c = sqrt_fast(cc * sq);
            snew = fabsf(u) + c;
            FQ = fmaf(Q, u, fqc * A * sq);
        }

        sAQF[nb][tid] = make_float4(A, Q, FQ, 0.f);
        int wv = __reduce_max_sync(0xFFFFFFFFu, __float_as_int(snew));
        if (lane == 0) wmax[wid] = wv;
        __syncthreads();
        if (wid == 0) {
            int v = __reduce_max_sync(0xFFFFFFFFu, (lane < NWARP) ? wmax[lane] : 0);
            if (lane == 0) {
                red_max_relaxed(&g_sync[t + 1].x, (unsigned)v);
                red_add_release(&g_sync[t + 1].y, 1u);   // un-held: no unacked prior STGs
            }
        }
        // edge publish AFTER the arrive (tid0: after its REDs; tid BT-1: after bar#2).
        // Value-gated by in-word tag; consumed by neighbor polls that resolve
        // well before that neighbor's global count-detect.
        if (tid == 0)      st_weak_v4(&g_edgeL[nb][cta], make_float4(A, Q, FQ, __int_as_float(t + 1)));
        if (tid == BT - 1) st_weak_v4(&g_edgeR[nb][cta], make_float4(A, Q, FQ, __int_as_float(t + 1)));
    }
}

extern "C" void kernel_launch(void* const* d_in, const int* in_sizes, int n_in,
                              void* d_out, int out_size) {
    const float* Rs         = (const float*)d_in[0];
    const float* sim_dat    = (const float*)d_in[1];
    const float* sdc        = (const float*)d_in[2];
    const float* input_data = (const float*)d_in[3];
    const int*   strides    = (const int*)d_in[4];

    int M = in_sizes[1] / 2;     // sim_dat is (2, M)
    int T = in_sizes[3];         // input_data length

    int nCTA = (M + BT - 1) / BT;   // 141 — 1 CTA/SM, all co-resident

    sim_init_kernel<<<2, 256>>>();
    sim_kernel<<<nCTA, BT>>>(Rs, sim_dat, sdc, input_data, strides, (float*)d_out, M, T);
}

// round 14
// speedup vs baseline: 1.4569x; 1.4569x over previous
#include <cuda_runtime.h>

#define BT 640
#define NWARP 20
#define RHO_F 1060.0f
#define CCFL_F 0.9f
#define EPS_AF 1e-6f
#define MAX_CTA 160
#define MAX_T 256

// Critical-role warps: B300 arbiter is hi-wid-first, so the serialized
// sync/reduce chain lives in the HIGHEST warps to win issue arbitration.
#define SPIN_TID  ((NWARP - 1) * 32)   // 608: sync-word spinner (wid 19 lane 0)
#define EDGEL_TID ((NWARP - 2) * 32)   // 576: left-edge poller  (wid 18 lane 0)
#define EDGER_TID ((NWARP - 3) * 32)   // 544: right-edge poller (wid 17 lane 0)

// Persistent scratch.
// g_sync[t] = {smax_bits (red.max), arrive_count (red.add)} — one 8B word per step.
__device__ uint2  g_sync[MAX_T];
__device__ float4 g_edgeL[2][MAX_CTA];   // [buf][cta] first-point {A,Q,FQ,tag}
__device__ float4 g_edgeR[2][MAX_CTA];   // [buf][cta] last-point  {A,Q,FQ,tag}

__device__ __forceinline__ uint2 ld_acq_v2(const uint2* p) {
    uint2 v;
    asm volatile("ld.acquire.gpu.global.v2.u32 {%0,%1}, [%2];"
                 : "=r"(v.x), "=r"(v.y) : "l"(p) : "memory");
    return v;
}
__device__ __forceinline__ float4 ld_acq_v4(const float4* p) {
    float4 v;
    asm volatile("ld.acquire.gpu.global.v4.f32 {%0,%1,%2,%3}, [%4];"
                 : "=f"(v.x), "=f"(v.y), "=f"(v.z), "=f"(v.w) : "l"(p) : "memory");
    return v;
}
__device__ __forceinline__ void st_weak_v4(float4* p, float4 v) {
    asm volatile("st.global.v4.f32 [%0], {%1,%2,%3,%4};"
                 :: "l"(p), "f"(v.x), "f"(v.y), "f"(v.z), "f"(v.w) : "memory");
}
__device__ __forceinline__ void red_max_relaxed(unsigned* p, unsigned v) {
    asm volatile("red.relaxed.gpu.global.max.u32 [%0], %1;" :: "l"(p), "r"(v) : "memory");
}
__device__ __forceinline__ void red_add_release(unsigned* p, unsigned v) {
    asm volatile("red.release.gpu.global.add.u32 [%0], %1;" :: "l"(p), "r"(v) : "memory");
}
__device__ __forceinline__ float sqrt_fast(float x) {
    float y; asm("sqrt.approx.f32 %0, %1;" : "=f"(y) : "f"(x)); return y;
}

__global__ void sim_init_kernel() {
    int i = blockIdx.x * blockDim.x + threadIdx.x;
    if (i < MAX_T) g_sync[i] = make_uint2(0u, 0u);
    if (i < 2 * MAX_CTA) {   // reset edge tags (replay safety)
        float tg = __int_as_float(-1);
        ((float4*)g_edgeL)[i].w = tg;
        ((float4*)g_edgeR)[i].w = tg;
    }
}

__global__ void __launch_bounds__(BT, 1) sim_kernel(
    const float* __restrict__ Rs,
    const float* __restrict__ sim_dat,      // (2, M)
    const float* __restrict__ sdc,          // (11, M)
    const float* __restrict__ input_data,   // (T,)
    const int*   __restrict__ strides,      // (3, 2)
    float*       __restrict__ out,          // (T, 3)
    int M, int T)
{
    __shared__ float4 sAQF[2][BT];    // packed state {A, Q, FQ, _}
    __shared__ int    wmax[NWARP];
    __shared__ float  bc[9];          // [0]=lam  [3..5]=left AQF  [6..8]=right AQF
    __shared__ float  sIn[256];

    const int tid  = threadIdx.x;
    const int lane = tid & 31;
    const int wid  = tid >> 5;
    const int cta  = blockIdx.x;
    const int nCTA = gridDim.x;
    const int gi   = cta * BT + tid;
    const bool active = gi < M;

    for (int i = tid; i < T; i += BT) sIn[i] = input_data[i];
    if (tid >= 3 && tid < 9) bc[tid] = 1.0f;   // defaults; domain-boundary CTAs never overwrite

    const int st0 = strides[0], st1 = strides[2], st2 = strides[4];
    const int en0 = strides[1] - 1, en1 = strides[3] - 1, en2 = strides[5] - 1;
    const int mid0 = (strides[0] + strides[1]) >> 1;
    const int mid1 = (strides[2] + strides[3]) >> 1;
    const int mid2 = (strides[4] + strides[5]) >> 1;

    const bool is_start = active && (gi == st0 || gi == st1 || gi == st2);
    const bool is_end   = active && (gi == en0 || gi == en1 || gi == en2);
    const bool interior = active && gi > 0 && gi < M - 1;
    const int  midv = (gi == mid0) ? 0 : (gi == mid1) ? 1 : (gi == mid2) ? 2 : -1;

    float A = 1.0f, Q = 0.0f, invA0 = 1.0f, beta = 1.0f, Rtot = 1.0f;
    if (active) {
        A = fmaxf(sim_dat[gi], EPS_AF);
        Q = 0.1f * sim_dat[M + gi];
        invA0 = __fdividef(1.0f, sdc[gi] + 0.5f);
        beta = sdc[M + gi] + 1.0f;
        if (is_end) {
            float R1 = sdc[7 * M + gi] + 0.5f;
            float R2 = sdc[8 * M + gi] + 0.5f;
            bool m1 = (gi >= strides[2]) && (gi < strides[3]);
            bool m2 = (gi >= strides[4]) && (gi < strides[5]);
            float rsv[4];
#pragma unroll
            for (int j = 0; j < 4; j++) {
                float x = Rs[j];
                rsv[j] = fmaxf(x, 0.0f) + log1pf(expf(-fabsf(x)));   // softplus
            }
            if (m1)      { R1 *= rsv[0]; R2 *= rsv[1]; }
            else if (m2) { R1 *= rsv[2]; R2 *= rsv[3]; }
            Rtot = R1 + R2;
        }
    }
    const float cc  = beta * (0.5f / RHO_F);
    const float fqc = beta * invA0 * (1.0f / (3.0f * RHO_F));

    // ---- prologue: state-0 derived quantities, publish ----
    float sq = 1.0f, FQ = 0.0f, sval = 0.0f;
    if (active) {
        sq = sqrt_fast(A * invA0);
        float u = __fdividef(Q, A);
        float c = sqrt_fast(cc * sq);
        sval = fabsf(u) + c;
        FQ = Q * u + fqc * A * sq;
    }
    sAQF[0][tid] = make_float4(A, Q, FQ, 0.f);
    if (tid == 0)      st_weak_v4(&g_edgeL[0][cta], make_float4(A, Q, FQ, __int_as_float(0)));
    if (tid == BT - 1) st_weak_v4(&g_edgeR[0][cta], make_float4(A, Q, FQ, __int_as_float(0)));
    {
        int wv = __reduce_max_sync(0xFFFFFFFFu, __float_as_int(sval));
        if (lane == 0) wmax[wid] = wv;
    }
    __syncthreads();
    if (wid == NWARP - 1) {
        int v = __reduce_max_sync(0xFFFFFFFFu, (lane < NWARP) ? wmax[lane] : 0);
        if (lane == 0) {
            red_max_relaxed(&g_sync[0].x, (unsigned)v);
            red_add_release(&g_sync[0].y, 1u);
        }
    }

    const bool haveL = tid > 0, haveR = tid < BT - 1;
    const bool pollL = (cta > 0), pollR = (cta + 1 < nCTA);

    for (int t = 0; t < T; ++t) {
        const int b = t & 1, nb = b ^ 1;

        // ---- PRE-BARRIER: stencil terms not needing lam ----
        // lam*0.5*smax = 0.45 (constant):
        //   A_new = [A + 0.45*(Ar-2A+Al)] - lam*0.5*(Qr-Ql)
        //   Q_new = [Q + 0.45*(Qr-2Q+Ql)] - lam*0.5*(Fr-Fl)
        float4 Lh, Rh;
        float dA1 = 0.f, dQ1 = 0.f, cA = A, cQ = Q;
        if (haveL && haveR) {
            Lh = sAQF[b][tid - 1]; Rh = sAQF[b][tid + 1];
            dA1 = 0.5f * (Rh.y - Lh.y);
            dQ1 = 0.5f * (Rh.z - Lh.z);
            cA  = fmaf(0.45f, Rh.x - 2.0f * A + Lh.x, A);
            cQ  = fmaf(0.45f, Rh.y - 2.0f * Q + Lh.y, Q);
        }
        const float P = beta * (sq - 1.0f);
        if (midv >= 0) out[t * 3 + midv] = P;
        const float Qend = is_end ? __fdividef(P, Rtot) : 0.0f;

        // ---- barrier + prefetch: scalar spins in the HIGHEST warps (arbiter priority) ----
        if (tid == SPIN_TID) {
            uint2 s;
            do { s = ld_acq_v2(&g_sync[t]); } while (s.y != (unsigned)nCTA);
            bc[0] = __fdividef(CCFL_F, __uint_as_float(s.x));   // ship lam, not smax
        } else if (tid == EDGEL_TID && pollL) {
            float4 e;
            do { e = ld_acq_v4(&g_edgeR[b][cta - 1]); } while (__float_as_int(e.w) != t);
            bc[3] = e.x; bc[4] = e.y; bc[5] = e.z;
        } else if (tid == EDGER_TID && pollR) {
            float4 e;
            do { e = ld_acq_v4(&g_edgeL[b][cta + 1]); } while (__float_as_int(e.w) != t);
            bc[6] = e.x; bc[7] = e.y; bc[8] = e.z;
        }
        __syncthreads();
        const float lam = bc[0];

        // edge threads: halo staged in bc — zero L2 on the post-barrier path
        if (!haveL || !haveR) {
            if (!haveL) { Lh.x = bc[3]; Lh.y = bc[4]; Lh.z = bc[5]; }
            else        { Lh = sAQF[b][tid - 1]; }
            if (!haveR) { Rh.x = bc[6]; Rh.y = bc[7]; Rh.z = bc[8]; }
            else        { Rh = sAQF[b][tid + 1]; }
            dA1 = 0.5f * (Rh.y - Lh.y);
            dQ1 = 0.5f * (Rh.z - Lh.z);
            cA  = fmaf(0.45f, Rh.x - 2.0f * A + Lh.x, A);
            cQ  = fmaf(0.45f, Rh.y - 2.0f * Q + Lh.y, Q);
        }

        // ---- POST-BARRIER: short chain ----
        float An = interior ? cA - lam * dA1 : A;
        float Qn = interior ? cQ - lam * dQ1 : Q;
        if (is_start) Qn = sIn[t];
        if (is_end)   Qn = Qend;
        An = fmaxf(An, EPS_AF);

        float snew = 0.0f;
        if (active) {
            A = An; Q = Qn;
            sq = sqrt_fast(A * invA0);
            float u = __fdividef(Q, A);
            float c = sqrt_fast(cc * sq);
            snew = fabsf(u) + c;
            FQ = fmaf(Q, u, fqc * A * sq);
        }

        // publish early (R10 order: before reduce/bar#2; in-word tags, weak stores)
        sAQF[nb][tid] = make_float4(A, Q, FQ, 0.f);
        if (tid == 0)      st_weak_v4(&g_edgeL[nb][cta], make_float4(A, Q, FQ, __int_as_float(t + 1)));
        if (tid == BT - 1) st_weak_v4(&g_edgeR[nb][cta], make_float4(A, Q, FQ, __int_as_float(t + 1)));
        int wv = __reduce_max_sync(0xFFFFFFFFu, __float_as_int(snew));
        if (lane == 0) wmax[wid] = wv;
        __syncthreads();
        if (wid == NWARP - 1) {   // highest warp owns the arrive chain too
            int v = __reduce_max_sync(0xFFFFFFFFu, (lane < NWARP) ? wmax[lane] : 0);
            if (lane == 0) {
                red_max_relaxed(&g_sync[t + 1].x, (unsigned)v);
                red_add_release(&g_sync[t + 1].y, 1u);   // release pairs with detect acquire
            }
        }
    }
}

extern "C" void kernel_launch(void* const* d_in, const int* in_sizes, int n_in,
                              void* d_out, int out_size) {
    const float* Rs         = (const float*)d_in[0];
    const float* sim_dat    = (const float*)d_in[1];
    const float* sdc        = (const float*)d_in[2];
    const float* input_data = (const float*)d_in[3];
    const int*   strides    = (const int*)d_in[4];

    int M = in_sizes[1] / 2;     // sim_dat is (2, M)
    int T = in_sizes[3];         // input_data length

    int nCTA = (M + BT - 1) / BT;   // 141 — 1 CTA/SM, all co-resident

    sim_init_kernel<<<2, 256>>>();
    sim_kernel<<<nCTA, BT>>>(Rs, sim_dat, sdc, input_data, strides, (float*)d_out, M, T);
}